// round 12
// baseline (speedup 1.0000x reference)
#include <cuda_runtime.h>
#include <cuda_bf16.h>

// EdgeDecoder: per-edge bilinear scores over 5 relations + softmax-expected rating.
//   z_user  [100000, 64] f32
//   z_movie [ 50000, 64] f32
//   rel_emb [     5, 64] f32
//   edge_label_index [2, E] int (32 or 64 — detected at runtime)
//   out [E] f32
//
// R12 = R11 body + DYNAMIC WARP-LEVEL WORK STEALING (single wave, 760 CTAs,
// ticket counter reset by prep each launch) + PARALLEL SOFTMAX.
//  - static scheduling left a 1.6-wave tail + per-CTA latency spread; one
//    wave with warp tickets (chunk = 16 pairs, ~5 tickets/warp, next ticket
//    prefetched) removes both. Deterministic: per-edge results don't depend
//    on which warp computes them.
//  - parallel softmax: each lane exps its own rel total; shfl-max + den/num
//    pair-reduce inside each 4-lane half. 13 SHFL/iter vs 15, 2 exps vs 5,
//    no 4-deep serial shfl gather.
// Retained: smem relD + softmax shift trick, 2-edge (cross-half) pairing,
// line-aligned lane mapping, value-splitting butterfly reduce, 32-bit offsets.

constexpr int H = 64;
constexpr int NBLOCKS = 760;            // 152 SMs x 5 CTAs (single wave)
constexpr int NWARPS  = NBLOCKS * 8;    // 256 threads/CTA
constexpr int CPAIRS  = 4;              // pairs per group per ticket (16/warp)

__device__ int      g_idx_is64;
__device__ unsigned g_ticket;
__device__ float    g_relD[4 * H];      // rel[r+1][h] - rel[0][h]

__global__ void prep_kernel(const float* __restrict__ rel_emb,
                            const void* __restrict__ edge_idx) {
    const int t = threadIdx.x;
    if (t < 4 * H) {
        const int r = t >> 6, h = t & 63;
        g_relD[t] = rel_emb[(r + 1) * H + h] - rel_emb[h];
    }
    if (t == 0) {
        g_ticket = NWARPS;   // first NWARPS tickets are statically assigned
        // int64-vs-int32 index detection: true int64 indices are all in
        // [0, 50000). int32 data reinterpreted as int64 gives lo + hi*2^32
        // with hi ~ U[0,50000): passing all 8 checks is ~impossible.
        const long long* p = (const long long*)edge_idx;
        int is64 = 1;
        #pragma unroll
        for (int i = 0; i < 8; i++) {
            long long v = p[i];
            if (v < 0 || v >= 50000) is64 = 0;
        }
        g_idx_is64 = is64;
    }
}

template <bool IS64>
__device__ __forceinline__ void idx_load4(
    const void* __restrict__ edge_idx, int E,
    int eA, int eB, int& s1, int& d1, int& s2, int& d2)
{
    if (IS64) {
        const long long* p = (const long long*)edge_idx;
        s1 = (int)__ldg(p + eA);
        d1 = (int)__ldg(p + (long long)E + eA);
        s2 = (int)__ldg(p + eB);
        d2 = (int)__ldg(p + (long long)E + eB);
    } else {
        const int* p = (const int*)edge_idx;
        s1 = __ldg(p + eA);
        d1 = __ldg(p + E + eA);
        s2 = __ldg(p + eB);
        d2 = __ldg(p + E + eB);
    }
}

template <bool IS64>
__device__ __forceinline__ void run_loop(
    const float* __restrict__ z_user,
    const float* __restrict__ z_movie,
    const void* __restrict__ edge_idx,
    float* __restrict__ out,
    int E, unsigned gwarp, int lane,
    const float* rel_lo, const float* rel_hi)
{
    const int sub = lane & 7;     // lane within 8-lane group
    const int grp = lane >> 3;    // group index within warp (0..3)
    const int P   = (E + 1) >> 1; // edge pairs; pair p -> edges (p, p+P)

    const float rlabel = (float)((sub & 3) + 1);
    const float r0mask = ((sub & 3) == 0) ? 1.f : 0.f;

    unsigned t = gwarp;
    while ((int)(t * (4 * CPAIRS)) < P) {
        const int base = (int)(t * (4 * CPAIRS));

        // prefetch next ticket; its ~318cyc latency hides under chunk work
        unsigned tn = 0;
        if (lane == 0) tn = atomicAdd(&g_ticket, 1u);
        tn = __shfl_sync(0xffffffffu, tn, 0);

        #pragma unroll
        for (int k = 0; k < CPAIRS; k++) {
            const int  p     = base + 4 * k + grp;   // groups read adjacent pairs
            const bool valid = (p < P);
            const int  pc    = valid ? p : (P - 1);  // clamped (safe loads)
            const int  eA    = pc;
            const int  eBr   = pc + P;
            const bool hasB  = (eBr < E);
            const int  eB    = hasB ? eBr : eA;

            int sA, dA, sB, dB;
            idx_load4<IS64>(edge_idx, E, eA, eB, sA, dA, sB, dB);

            const float* uA = z_user  + sA * H;
            const float* mA = z_movie + dA * H;
            const float* uB = z_user  + sB * H;
            const float* mB = z_movie + dB * H;

            const float4 zsA0 = *reinterpret_cast<const float4*>(uA + 4 * sub);
            const float4 zdA0 = *reinterpret_cast<const float4*>(mA + 4 * sub);
            const float4 zsA1 = *reinterpret_cast<const float4*>(uA + 32 + 4 * sub);
            const float4 zdA1 = *reinterpret_cast<const float4*>(mA + 32 + 4 * sub);
            const float4 zsB0 = *reinterpret_cast<const float4*>(uB + 4 * sub);
            const float4 zdB0 = *reinterpret_cast<const float4*>(mB + 4 * sub);
            const float4 zsB1 = *reinterpret_cast<const float4*>(uB + 32 + 4 * sub);
            const float4 zdB1 = *reinterpret_cast<const float4*>(mB + 32 + 4 * sub);

            // ---- elementwise products
            const float a0 = zsA0.x * zdA0.x, a1 = zsA0.y * zdA0.y,
                        a2 = zsA0.z * zdA0.z, a3 = zsA0.w * zdA0.w;
            const float a4 = zsA1.x * zdA1.x, a5 = zsA1.y * zdA1.y,
                        a6 = zsA1.z * zdA1.z, a7 = zsA1.w * zdA1.w;
            const float b0 = zsB0.x * zdB0.x, b1 = zsB0.y * zdB0.y,
                        b2 = zsB0.z * zdB0.z, b3 = zsB0.w * zdB0.w;
            const float b4 = zsB1.x * zdB1.x, b5 = zsB1.y * zdB1.y,
                        b6 = zsB1.z * zdB1.z, b7 = zsB1.w * zdB1.w;

            // ---- per-lane score partials (relD from smem, shared by A & B)
            float x[8];   // x[0..3]=scA_r, x[4..7]=scB_r
            #pragma unroll
            for (int r = 0; r < 4; r++) {
                const float4 r0 = *reinterpret_cast<const float4*>(rel_lo + r * H);
                const float4 r1 = *reinterpret_cast<const float4*>(rel_hi + r * H);
                x[r]     = fmaf(a0, r0.x, fmaf(a1, r0.y, fmaf(a2, r0.z, a3 * r0.w)))
                         + fmaf(a4, r1.x, fmaf(a5, r1.y, fmaf(a6, r1.z, a7 * r1.w)));
                x[4 + r] = fmaf(b0, r0.x, fmaf(b1, r0.y, fmaf(b2, r0.z, b3 * r0.w)))
                         + fmaf(b4, r1.x, fmaf(b5, r1.y, fmaf(b6, r1.z, b7 * r1.w)));
            }

            // ---- value-splitting butterfly reduce (8 values over 8 lanes)
            const bool hi4 = (sub & 4) != 0;
            float k4[4];
            #pragma unroll
            for (int i = 0; i < 4; i++) {
                const float keep = hi4 ? x[4 + i] : x[i];
                const float give = hi4 ? x[i]     : x[4 + i];
                k4[i] = keep + __shfl_xor_sync(0xffffffffu, give, 4);
            }
            const bool hi2 = (sub & 2) != 0;
            float k2[2];
            {
                const float kp0 = hi2 ? k4[2] : k4[0];
                const float gv0 = hi2 ? k4[0] : k4[2];
                const float kp1 = hi2 ? k4[3] : k4[1];
                const float gv1 = hi2 ? k4[1] : k4[3];
                k2[0] = kp0 + __shfl_xor_sync(0xffffffffu, gv0, 2);
                k2[1] = kp1 + __shfl_xor_sync(0xffffffffu, gv1, 2);
            }
            const bool hi1 = (sub & 1) != 0;
            const float kp = hi1 ? k2[1] : k2[0];
            const float gv = hi1 ? k2[0] : k2[1];
            const float tot = kp + __shfl_xor_sync(0xffffffffu, gv, 1);
            // lane (8g + r) holds scA_r total; lane (8g + 4 + r) holds scB_r

            // ---- parallel softmax within each 4-lane half
            // (xor 1 and 2 stay inside the half; score'[0]=0 handled by r0mask)
            float m = fmaxf(tot, __shfl_xor_sync(0xffffffffu, tot, 1));
            m = fmaxf(m, __shfl_xor_sync(0xffffffffu, m, 2));
            m = fmaxf(m, 0.f);
            const float ex = __expf(tot - m);
            float den = fmaf(r0mask, __expf(-m), ex);   // + label-0 term once
            float num = ex * rlabel;
            den += __shfl_xor_sync(0xffffffffu, den, 1);
            num += __shfl_xor_sync(0xffffffffu, num, 1);
            den += __shfl_xor_sync(0xffffffffu, den, 2);
            num += __shfl_xor_sync(0xffffffffu, num, 2);
            const float res = num / den;

            if ((sub & 3) == 0) {
                if (sub == 0) { if (valid)         out[pc]     = res; }
                else          { if (valid && hasB) out[pc + P] = res; }
            }
        }
        t = tn;
    }
}

__global__ __launch_bounds__(256, 5) void edge_decoder_kernel(
    const float* __restrict__ z_user,
    const float* __restrict__ z_movie,
    const void* __restrict__ edge_idx,
    float* __restrict__ out,
    int E)
{
    __shared__ float s_rel[4 * H];
    for (int t = threadIdx.x; t < 4 * H; t += 256)
        s_rel[t] = g_relD[t];
    __syncthreads();

    const int lane  = threadIdx.x & 31;
    const int sub   = lane & 7;
    const unsigned gwarp = (blockIdx.x * 256 + threadIdx.x) >> 5;

    const float* rel_lo = s_rel + 4 * sub;        // floats [4sub..4sub+3]
    const float* rel_hi = s_rel + 32 + 4 * sub;   // floats [32+4sub..+3]

    if (g_idx_is64)
        run_loop<true >(z_user, z_movie, edge_idx, out, E, gwarp, lane, rel_lo, rel_hi);
    else
        run_loop<false>(z_user, z_movie, edge_idx, out, E, gwarp, lane, rel_lo, rel_hi);
}

extern "C" void kernel_launch(void* const* d_in, const int* in_sizes, int n_in,
                              void* d_out, int out_size) {
    const float* z_user  = (const float*)d_in[0];
    const float* z_movie = (const float*)d_in[1];
    const float* rel_emb = (const float*)d_in[2];
    const void*  eidx    = d_in[3];
    float* out = (float*)d_out;

    const int E = out_size;  // one rating per edge

    prep_kernel<<<1, 256>>>(rel_emb, eidx);

    // Single wave + dynamic stealing: exactly 5 CTAs/SM x 152 SMs.
    edge_decoder_kernel<<<NBLOCKS, 256>>>(z_user, z_movie, eidx, out, E);
}

// round 13
// speedup vs baseline: 1.6064x; 1.6064x over previous
#include <cuda_runtime.h>
#include <cuda_bf16.h>

// EdgeDecoder: per-edge bilinear scores over 5 relations + softmax-expected rating.
//   z_user  [100000, 64] f32
//   z_movie [ 50000, 64] f32
//   rel_emb [     5, 64] f32
//   edge_label_index [2, E] int (32 or 64 — detected at runtime)
//   out [E] f32
//
// R13 = R9/R11 base (best: 47.6us; static grid-stride, 1216 CTAs, no reg cap,
// no dynamic stealing — R12's stealing+reg-cap spilled to local mem and
// regressed 69%) + EXACTLY ONE change:
//   PARALLEL SOFTMAX: after the value-splitting butterfly, lane (8g+j) holds
//   total j (j=0..3 edge-A rels, 4..7 edge-B rels). Instead of 4 gather
//   shuffles + an 8-lane serial 5-exp softmax, each lane exps its OWN score;
//   max/den/num reduce with 6 xor-shuffles inside each 4-lane half; the
//   label-0 shift term exp(-m) is added once per half via a lane mask.
//   ~8 warp-instructions and the 4-deep serial shfl chain removed per iter.
// Retained: smem relD + softmax shift trick (relD[r]=rel[r+1]-rel[0]),
// 2-edge strided pairing, line-aligned lane mapping, value-splitting
// butterfly (7 SHFL), is64/is32 template split, 32-bit offsets, 1216 blocks.

constexpr int H = 64;

__device__ int   g_idx_is64;
__device__ float g_relD[4 * H];   // rel[r+1][h] - rel[0][h]

__global__ void prep_kernel(const float* __restrict__ rel_emb,
                            const void* __restrict__ edge_idx) {
    const int t = threadIdx.x;
    if (t < 4 * H) {
        const int r = t >> 6, h = t & 63;
        g_relD[t] = rel_emb[(r + 1) * H + h] - rel_emb[h];
    }
    if (t == 0) {
        // int64-vs-int32 index detection: true int64 indices are all in
        // [0, 50000). int32 data reinterpreted as int64 gives lo + hi*2^32
        // with hi ~ U[0,50000): passing all 8 checks is ~impossible.
        const long long* p = (const long long*)edge_idx;
        int is64 = 1;
        #pragma unroll
        for (int i = 0; i < 8; i++) {
            long long v = p[i];
            if (v < 0 || v >= 50000) is64 = 0;
        }
        g_idx_is64 = is64;
    }
}

template <bool IS64>
__device__ __forceinline__ void run_loop(
    const float* __restrict__ z_user,
    const float* __restrict__ z_movie,
    const void* __restrict__ edge_idx,
    float* __restrict__ out,
    int E, int g0, int ngroups, int sub,
    const float* rel_lo, const float* rel_hi)
{
    const long long* p64 = (const long long*)edge_idx;
    const int*       p32 = (const int*)edge_idx;

    // lane-constant softmax helpers: lane's relation label r+1 and the
    // "add exp(-m) once per 4-lane half" mask.
    const float rlabel = (float)((sub & 3) + 1);
    const float r0mask = ((sub & 3) == 0) ? 1.f : 0.f;

    for (int e = g0; e < E; e += 2 * ngroups) {
        const int  e2   = e + ngroups;
        const bool has2 = (e2 < E);

        // ---- issue ALL loads up front: 2 index pairs, then 8 gather float4s
        int sA, dA, sB, dB;
        if (IS64) {
            sA = (int)__ldg(p64 + e);
            dA = (int)__ldg(p64 + (long long)E + e);
            sB = has2 ? (int)__ldg(p64 + e2) : 0;
            dB = has2 ? (int)__ldg(p64 + (long long)E + e2) : 0;
        } else {
            sA = __ldg(p32 + e);
            dA = __ldg(p32 + E + e);
            sB = has2 ? __ldg(p32 + e2) : 0;
            dB = has2 ? __ldg(p32 + E + e2) : 0;
        }

        const float* uA = z_user  + sA * H;
        const float* mA = z_movie + dA * H;
        const float* uB = z_user  + sB * H;
        const float* mB = z_movie + dB * H;

        const float4 zsA0 = *reinterpret_cast<const float4*>(uA + 4 * sub);
        const float4 zdA0 = *reinterpret_cast<const float4*>(mA + 4 * sub);
        const float4 zsA1 = *reinterpret_cast<const float4*>(uA + 32 + 4 * sub);
        const float4 zdA1 = *reinterpret_cast<const float4*>(mA + 32 + 4 * sub);
        const float4 zsB0 = *reinterpret_cast<const float4*>(uB + 4 * sub);
        const float4 zdB0 = *reinterpret_cast<const float4*>(mB + 4 * sub);
        const float4 zsB1 = *reinterpret_cast<const float4*>(uB + 32 + 4 * sub);
        const float4 zdB1 = *reinterpret_cast<const float4*>(mB + 32 + 4 * sub);

        // ---- elementwise products
        const float a0 = zsA0.x * zdA0.x, a1 = zsA0.y * zdA0.y,
                    a2 = zsA0.z * zdA0.z, a3 = zsA0.w * zdA0.w;
        const float a4 = zsA1.x * zdA1.x, a5 = zsA1.y * zdA1.y,
                    a6 = zsA1.z * zdA1.z, a7 = zsA1.w * zdA1.w;
        const float b0 = zsB0.x * zdB0.x, b1 = zsB0.y * zdB0.y,
                    b2 = zsB0.z * zdB0.z, b3 = zsB0.w * zdB0.w;
        const float b4 = zsB1.x * zdB1.x, b5 = zsB1.y * zdB1.y,
                    b6 = zsB1.z * zdB1.z, b7 = zsB1.w * zdB1.w;

        // ---- per-lane score partials (relD from smem, shared by A & B)
        float x[8];   // x[0..3]=scA_r, x[4..7]=scB_r
        #pragma unroll
        for (int r = 0; r < 4; r++) {
            const float4 r0 = *reinterpret_cast<const float4*>(rel_lo + r * H);
            const float4 r1 = *reinterpret_cast<const float4*>(rel_hi + r * H);
            x[r]     = fmaf(a0, r0.x, fmaf(a1, r0.y, fmaf(a2, r0.z, a3 * r0.w)))
                     + fmaf(a4, r1.x, fmaf(a5, r1.y, fmaf(a6, r1.z, a7 * r1.w)));
            x[4 + r] = fmaf(b0, r0.x, fmaf(b1, r0.y, fmaf(b2, r0.z, b3 * r0.w)))
                     + fmaf(b4, r1.x, fmaf(b5, r1.y, fmaf(b6, r1.z, b7 * r1.w)));
        }

        // ---- value-splitting butterfly reduce (8 values over 8 lanes)
        const bool hi4 = (sub & 4) != 0;
        float k4[4];
        #pragma unroll
        for (int i = 0; i < 4; i++) {
            const float keep = hi4 ? x[4 + i] : x[i];
            const float give = hi4 ? x[i]     : x[4 + i];
            k4[i] = keep + __shfl_xor_sync(0xffffffffu, give, 4);
        }
        const bool hi2 = (sub & 2) != 0;
        float k2[2];
        {
            const float kp0 = hi2 ? k4[2] : k4[0];
            const float gv0 = hi2 ? k4[0] : k4[2];
            const float kp1 = hi2 ? k4[3] : k4[1];
            const float gv1 = hi2 ? k4[1] : k4[3];
            k2[0] = kp0 + __shfl_xor_sync(0xffffffffu, gv0, 2);
            k2[1] = kp1 + __shfl_xor_sync(0xffffffffu, gv1, 2);
        }
        const bool hi1 = (sub & 1) != 0;
        const float kp = hi1 ? k2[1] : k2[0];
        const float gv = hi1 ? k2[0] : k2[1];
        const float tot = kp + __shfl_xor_sync(0xffffffffu, gv, 1);
        // lane (8g + r) holds scA_r total; lane (8g + 4 + r) holds scB_r

        // ---- parallel softmax inside each 4-lane half (xor 1,2 stay in-half)
        // score'[0]=0 handled by the shift trick: den gets exp(-m) once.
        float m = fmaxf(tot, __shfl_xor_sync(0xffffffffu, tot, 1));
        m = fmaxf(m, __shfl_xor_sync(0xffffffffu, m, 2));
        m = fmaxf(m, 0.f);
        const float ex = __expf(tot - m);
        float den = fmaf(r0mask, __expf(-m), ex);
        float num = ex * rlabel;
        den += __shfl_xor_sync(0xffffffffu, den, 1);
        num += __shfl_xor_sync(0xffffffffu, num, 1);
        den += __shfl_xor_sync(0xffffffffu, den, 2);
        num += __shfl_xor_sync(0xffffffffu, num, 2);
        const float res = num / den;

        // lanes sub==0 (edge A) and sub==4 (edge B) write out
        if ((sub & 3) == 0) {
            if (sub == 0)  out[e]  = res;
            else if (has2) out[e2] = res;
        }
    }
}

__global__ __launch_bounds__(256) void edge_decoder_kernel(
    const float* __restrict__ z_user,
    const float* __restrict__ z_movie,
    const void* __restrict__ edge_idx,
    float* __restrict__ out,
    int E)
{
    __shared__ float s_rel[4 * H];
    for (int t = threadIdx.x; t < 4 * H; t += 256)
        s_rel[t] = g_relD[t];
    __syncthreads();

    const int tid     = blockIdx.x * blockDim.x + threadIdx.x;
    const int sub     = threadIdx.x & 7;                 // lane within 8-lane group
    const int ngroups = (gridDim.x * blockDim.x) >> 3;   // total edge groups
    const int g0      = tid >> 3;

    const float* rel_lo = s_rel + 4 * sub;        // floats [4sub..4sub+3]
    const float* rel_hi = s_rel + 32 + 4 * sub;   // floats [32+4sub..+3]

    if (g_idx_is64)
        run_loop<true >(z_user, z_movie, edge_idx, out, E, g0, ngroups, sub, rel_lo, rel_hi);
    else
        run_loop<false>(z_user, z_movie, edge_idx, out, E, g0, ngroups, sub, rel_lo, rel_hi);
}

extern "C" void kernel_launch(void* const* d_in, const int* in_sizes, int n_in,
                              void* d_out, int out_size) {
    const float* z_user  = (const float*)d_in[0];
    const float* z_movie = (const float*)d_in[1];
    const float* rel_emb = (const float*)d_in[2];
    const void*  eidx    = d_in[3];
    float* out = (float*)d_out;

    const int E = out_size;  // one rating per edge

    prep_kernel<<<1, 256>>>(rel_emb, eidx);

    // R9's best grid: 1216 CTAs (~1.6 waves at 5 CTAs/SM) — ragged backfill
    // beats both a single static wave (R8) and dynamic stealing (R12).
    const int threads = 256;
    const int blocks  = 152 * 8;
    edge_decoder_kernel<<<blocks, threads>>>(z_user, z_movie, eidx, out, E);
}

// round 14
// speedup vs baseline: 1.6763x; 1.0435x over previous
#include <cuda_runtime.h>
#include <cuda_bf16.h>

// EdgeDecoder: per-edge bilinear scores over 5 relations + softmax-expected rating.
//   z_user  [100000, 64] f32
//   z_movie [ 50000, 64] f32
//   rel_emb [     5, 64] f32
//   edge_label_index [2, E] int (32 or 64 — detected at runtime)
//   out [E] f32
//
// R14 = R13 body + ONE change: 128-THREAD BLOCKS.
//   Regfile math: 65536 regs/SM / (46 regs x 32 lanes) = 44.5 warps. 256-thread
//   CTAs quantize to 5 CTAs = 40 warps; 128-thread CTAs reach 11 CTAs = 44
//   warps (+10% resident warps / in-flight gathers) with NO register squeeze
//   (R10 showed forcing regs down costs remat instructions). Finer CTA
//   granularity also smooths the wave tail. Grid = 1.5 waves of capacity.
// Retained (R13): parallel softmax in 4-lane halves, value-splitting
// butterfly (7 SHFL), smem relD + softmax shift trick, 2-edge strided
// pairing, line-aligned lane mapping, is64/is32 split, 32-bit offsets.

constexpr int H = 64;
constexpr int TPB = 128;

__device__ int   g_idx_is64;
__device__ float g_relD[4 * H];   // rel[r+1][h] - rel[0][h]

__global__ void prep_kernel(const float* __restrict__ rel_emb,
                            const void* __restrict__ edge_idx) {
    const int t = threadIdx.x;
    if (t < 4 * H) {
        const int r = t >> 6, h = t & 63;
        g_relD[t] = rel_emb[(r + 1) * H + h] - rel_emb[h];
    }
    if (t == 0) {
        // int64-vs-int32 index detection: true int64 indices are all in
        // [0, 50000). int32 data reinterpreted as int64 gives lo + hi*2^32
        // with hi ~ U[0,50000): passing all 8 checks is ~impossible.
        const long long* p = (const long long*)edge_idx;
        int is64 = 1;
        #pragma unroll
        for (int i = 0; i < 8; i++) {
            long long v = p[i];
            if (v < 0 || v >= 50000) is64 = 0;
        }
        g_idx_is64 = is64;
    }
}

template <bool IS64>
__device__ __forceinline__ void run_loop(
    const float* __restrict__ z_user,
    const float* __restrict__ z_movie,
    const void* __restrict__ edge_idx,
    float* __restrict__ out,
    int E, int g0, int ngroups, int sub,
    const float* rel_lo, const float* rel_hi)
{
    const long long* p64 = (const long long*)edge_idx;
    const int*       p32 = (const int*)edge_idx;

    // lane-constant softmax helpers: lane's relation label r+1 and the
    // "add exp(-m) once per 4-lane half" mask.
    const float rlabel = (float)((sub & 3) + 1);
    const float r0mask = ((sub & 3) == 0) ? 1.f : 0.f;

    for (int e = g0; e < E; e += 2 * ngroups) {
        const int  e2   = e + ngroups;
        const bool has2 = (e2 < E);

        // ---- issue ALL loads up front: 2 index pairs, then 8 gather float4s
        int sA, dA, sB, dB;
        if (IS64) {
            sA = (int)__ldg(p64 + e);
            dA = (int)__ldg(p64 + (long long)E + e);
            sB = has2 ? (int)__ldg(p64 + e2) : 0;
            dB = has2 ? (int)__ldg(p64 + (long long)E + e2) : 0;
        } else {
            sA = __ldg(p32 + e);
            dA = __ldg(p32 + E + e);
            sB = has2 ? __ldg(p32 + e2) : 0;
            dB = has2 ? __ldg(p32 + E + e2) : 0;
        }

        const float* uA = z_user  + sA * H;
        const float* mA = z_movie + dA * H;
        const float* uB = z_user  + sB * H;
        const float* mB = z_movie + dB * H;

        const float4 zsA0 = *reinterpret_cast<const float4*>(uA + 4 * sub);
        const float4 zdA0 = *reinterpret_cast<const float4*>(mA + 4 * sub);
        const float4 zsA1 = *reinterpret_cast<const float4*>(uA + 32 + 4 * sub);
        const float4 zdA1 = *reinterpret_cast<const float4*>(mA + 32 + 4 * sub);
        const float4 zsB0 = *reinterpret_cast<const float4*>(uB + 4 * sub);
        const float4 zdB0 = *reinterpret_cast<const float4*>(mB + 4 * sub);
        const float4 zsB1 = *reinterpret_cast<const float4*>(uB + 32 + 4 * sub);
        const float4 zdB1 = *reinterpret_cast<const float4*>(mB + 32 + 4 * sub);

        // ---- elementwise products
        const float a0 = zsA0.x * zdA0.x, a1 = zsA0.y * zdA0.y,
                    a2 = zsA0.z * zdA0.z, a3 = zsA0.w * zdA0.w;
        const float a4 = zsA1.x * zdA1.x, a5 = zsA1.y * zdA1.y,
                    a6 = zsA1.z * zdA1.z, a7 = zsA1.w * zdA1.w;
        const float b0 = zsB0.x * zdB0.x, b1 = zsB0.y * zdB0.y,
                    b2 = zsB0.z * zdB0.z, b3 = zsB0.w * zdB0.w;
        const float b4 = zsB1.x * zdB1.x, b5 = zsB1.y * zdB1.y,
                    b6 = zsB1.z * zdB1.z, b7 = zsB1.w * zdB1.w;

        // ---- per-lane score partials (relD from smem, shared by A & B)
        float x[8];   // x[0..3]=scA_r, x[4..7]=scB_r
        #pragma unroll
        for (int r = 0; r < 4; r++) {
            const float4 r0 = *reinterpret_cast<const float4*>(rel_lo + r * H);
            const float4 r1 = *reinterpret_cast<const float4*>(rel_hi + r * H);
            x[r]     = fmaf(a0, r0.x, fmaf(a1, r0.y, fmaf(a2, r0.z, a3 * r0.w)))
                     + fmaf(a4, r1.x, fmaf(a5, r1.y, fmaf(a6, r1.z, a7 * r1.w)));
            x[4 + r] = fmaf(b0, r0.x, fmaf(b1, r0.y, fmaf(b2, r0.z, b3 * r0.w)))
                     + fmaf(b4, r1.x, fmaf(b5, r1.y, fmaf(b6, r1.z, b7 * r1.w)));
        }

        // ---- value-splitting butterfly reduce (8 values over 8 lanes)
        const bool hi4 = (sub & 4) != 0;
        float k4[4];
        #pragma unroll
        for (int i = 0; i < 4; i++) {
            const float keep = hi4 ? x[4 + i] : x[i];
            const float give = hi4 ? x[i]     : x[4 + i];
            k4[i] = keep + __shfl_xor_sync(0xffffffffu, give, 4);
        }
        const bool hi2 = (sub & 2) != 0;
        float k2[2];
        {
            const float kp0 = hi2 ? k4[2] : k4[0];
            const float gv0 = hi2 ? k4[0] : k4[2];
            const float kp1 = hi2 ? k4[3] : k4[1];
            const float gv1 = hi2 ? k4[1] : k4[3];
            k2[0] = kp0 + __shfl_xor_sync(0xffffffffu, gv0, 2);
            k2[1] = kp1 + __shfl_xor_sync(0xffffffffu, gv1, 2);
        }
        const bool hi1 = (sub & 1) != 0;
        const float kp = hi1 ? k2[1] : k2[0];
        const float gv = hi1 ? k2[0] : k2[1];
        const float tot = kp + __shfl_xor_sync(0xffffffffu, gv, 1);
        // lane (8g + r) holds scA_r total; lane (8g + 4 + r) holds scB_r

        // ---- parallel softmax inside each 4-lane half (xor 1,2 stay in-half)
        // score'[0]=0 handled by the shift trick: den gets exp(-m) once.
        float m = fmaxf(tot, __shfl_xor_sync(0xffffffffu, tot, 1));
        m = fmaxf(m, __shfl_xor_sync(0xffffffffu, m, 2));
        m = fmaxf(m, 0.f);
        const float ex = __expf(tot - m);
        float den = fmaf(r0mask, __expf(-m), ex);
        float num = ex * rlabel;
        den += __shfl_xor_sync(0xffffffffu, den, 1);
        num += __shfl_xor_sync(0xffffffffu, num, 1);
        den += __shfl_xor_sync(0xffffffffu, den, 2);
        num += __shfl_xor_sync(0xffffffffu, num, 2);
        const float res = num / den;

        // lanes sub==0 (edge A) and sub==4 (edge B) write out
        if ((sub & 3) == 0) {
            if (sub == 0)  out[e]  = res;
            else if (has2) out[e2] = res;
        }
    }
}

__global__ __launch_bounds__(TPB) void edge_decoder_kernel(
    const float* __restrict__ z_user,
    const float* __restrict__ z_movie,
    const void* __restrict__ edge_idx,
    float* __restrict__ out,
    int E)
{
    __shared__ float s_rel[4 * H];
    for (int t = threadIdx.x; t < 4 * H; t += TPB)
        s_rel[t] = g_relD[t];
    __syncthreads();

    const int tid     = blockIdx.x * TPB + threadIdx.x;
    const int sub     = threadIdx.x & 7;                 // lane within 8-lane group
    const int ngroups = (gridDim.x * TPB) >> 3;          // total edge groups
    const int g0      = tid >> 3;

    const float* rel_lo = s_rel + 4 * sub;        // floats [4sub..4sub+3]
    const float* rel_hi = s_rel + 32 + 4 * sub;   // floats [32+4sub..+3]

    if (g_idx_is64)
        run_loop<true >(z_user, z_movie, edge_idx, out, E, g0, ngroups, sub, rel_lo, rel_hi);
    else
        run_loop<false>(z_user, z_movie, edge_idx, out, E, g0, ngroups, sub, rel_lo, rel_hi);
}

extern "C" void kernel_launch(void* const* d_in, const int* in_sizes, int n_in,
                              void* d_out, int out_size) {
    const float* z_user  = (const float*)d_in[0];
    const float* z_movie = (const float*)d_in[1];
    const float* rel_emb = (const float*)d_in[2];
    const void*  eidx    = d_in[3];
    float* out = (float*)d_out;

    const int E = out_size;  // one rating per edge

    prep_kernel<<<1, 256>>>(rel_emb, eidx);

    // 128-thread CTAs: 11 CTAs/SM at 46 regs -> 44 warps/SM (regfile limit).
    // Grid = 1.5x resident capacity (6688) for ragged-wave backfill.
    const int blocks = 10032;
    edge_decoder_kernel<<<blocks, TPB>>>(z_user, z_movie, eidx, out, E);
}